// round 7
// baseline (speedup 1.0000x reference)
#include <cuda_runtime.h>
#include <cuda_bf16.h>
#include <math.h>
#include <stdint.h>

// Problem constants
#define BB 64
#define TT 64
#define LL 400
#define EE 256
#define HH 512
#define H2 1024      // 2H
#define H4 2048      // 4H
#define BH (BB*HH)   // 32768

// d_out layout: outputs[T,B,H] | h[B,H] | c[B,H] | attn[T,B,L] | p_gens[T,B,1]
#define OUT_OUTPUTS 0
#define OUT_H  2097152
#define OUT_C  2129920
#define OUT_ATTN 2162688
#define OUT_PG 3801088

// ---------------- scratch (static device arrays; no allocation) ----------------
__device__ float g_enc_feat[BB*LL*HH];       // 52.4 MB
__device__ float g_Wx[H4*EE];
__device__ float g_Whh[H4*HH];
__device__ float g_bcomb[H4];
__device__ float g_u[EE];
__device__ float g_sx[TT*BB];
__device__ float g_gx_all[TT*BB*H4];         // x-part of gates (incl bias), all t
__device__ float g_h_all[TT*BB*HH];
__device__ float g_c_all[TT*BB*HH];
__device__ float g_dec_all[TT*BB*HH];
__device__ float g_e_all[TT*BB*LL];
__device__ float g_ctx_all[TT*BB*H2];

__device__ __forceinline__ float sigmoidf_(float x) { return 1.f/(1.f+__expf(-x)); }
// fast-but-accurate tanh: abs err ~1e-7 (NOT tanh.approx, which is ~6e-4)
__device__ __forceinline__ float ftanh(float x) {
    float e = __expf(2.f*x);
    return 1.f - __fdividef(2.f, e + 1.f);
}
__device__ __forceinline__ uint32_t packbf2(float a, float b) {
    __nv_bfloat162 t = __floats2bfloat162_rn(a, b);
    return *reinterpret_cast<uint32_t*>(&t);
}
__device__ __forceinline__ float residf(float a) {
    return a - __bfloat162float(__float2bfloat16(a));
}
// mma.sync m16n8k16 bf16 -> f32 accum (arch-agnostic tensor core path)
__device__ __forceinline__ void mma16816(float* d, const uint32_t* a, const uint32_t* b) {
    asm volatile(
        "mma.sync.aligned.m16n8k16.row.col.f32.bf16.bf16.f32 "
        "{%0,%1,%2,%3}, {%4,%5,%6,%7}, {%8,%9}, {%0,%1,%2,%3};\n"
        : "+f"(d[0]), "+f"(d[1]), "+f"(d[2]), "+f"(d[3])
        : "r"(a[0]), "r"(a[1]), "r"(a[2]), "r"(a[3]), "r"(b[0]), "r"(b[1]));
}

// ---------------------------------------------------------------------------
// bf16x3 tensor-core GEMM: C[m,n] = [A0|A1][m,:].W[n,:] + bias[n]
// fp32 in/out. A sources row-major (K-major), W [N,K] row-major.
// M,N multiples of 128; K multiple of 32; concat split w0 multiple of 16.
// Tile 128x128, BK=32, 256 threads = 8 warps (4M x 2N), each warp 32x64.
// ---------------------------------------------------------------------------
__global__ __launch_bounds__(256) void k_bmma(
    const float* __restrict__ A0, int w0,
    const float* __restrict__ A1, int w1,
    const float* __restrict__ W, const float* __restrict__ bias,
    float* __restrict__ C, int N)
{
    // padded stride 18 u32 (36 bf16) per row -> conflict-free quad access
    __shared__ uint32_t Ahi[128*18], Alo[128*18], Bhi[128*18], Blo[128*18];
    int tid = threadIdx.x;
    int lane = tid & 31, wid = tid >> 5;
    int wm = (wid & 3)*32, wn = (wid >> 2)*64;
    int K = w0 + w1;

    float acc[2][8][4];
    #pragma unroll
    for (int mi = 0; mi < 2; mi++)
        #pragma unroll
        for (int ni = 0; ni < 8; ni++)
            #pragma unroll
            for (int q = 0; q < 4; q++) acc[mi][ni][q] = 0.f;

    int lrow = tid >> 1;             // conversion row 0..127
    int lcol = (tid & 1)*16;         // float col base within 32-chunk
    size_t aRow = (size_t)blockIdx.y*128 + lrow;
    size_t wRow = (size_t)blockIdx.x*128 + lrow;
    int sbase = lrow*18 + (lcol >> 1);
    int gq = lane >> 2, tq = lane & 3;

    for (int kc = 0; kc < K; kc += 32) {
        int kg = kc + lcol;
        const float* asrc = (kg < w0) ? A0 + aRow*w0 + kg
                                      : A1 + aRow*w1 + (kg - w0);
        const float* wsrc = W + wRow*K + kg;
        #pragma unroll
        for (int g = 0; g < 4; g++) {
            float4 f = *(const float4*)(asrc + g*4);
            Ahi[sbase + g*2]     = packbf2(f.x, f.y);
            Ahi[sbase + g*2 + 1] = packbf2(f.z, f.w);
            Alo[sbase + g*2]     = packbf2(residf(f.x), residf(f.y));
            Alo[sbase + g*2 + 1] = packbf2(residf(f.z), residf(f.w));
            float4 h = *(const float4*)(wsrc + g*4);
            Bhi[sbase + g*2]     = packbf2(h.x, h.y);
            Bhi[sbase + g*2 + 1] = packbf2(h.z, h.w);
            Blo[sbase + g*2]     = packbf2(residf(h.x), residf(h.y));
            Blo[sbase + g*2 + 1] = packbf2(residf(h.z), residf(h.w));
        }
        __syncthreads();
        #pragma unroll
        for (int ks = 0; ks < 2; ks++) {
            int kb = ks*8 + tq;
            uint32_t ah[2][4], al[2][4];
            #pragma unroll
            for (int mi = 0; mi < 2; mi++) {
                int r = wm + mi*16 + gq;
                ah[mi][0] = Ahi[r*18 + kb];
                ah[mi][1] = Ahi[(r+8)*18 + kb];
                ah[mi][2] = Ahi[r*18 + kb + 4];
                ah[mi][3] = Ahi[(r+8)*18 + kb + 4];
                al[mi][0] = Alo[r*18 + kb];
                al[mi][1] = Alo[(r+8)*18 + kb];
                al[mi][2] = Alo[r*18 + kb + 4];
                al[mi][3] = Alo[(r+8)*18 + kb + 4];
            }
            #pragma unroll
            for (int ni = 0; ni < 8; ni++) {
                int n = wn + ni*8 + gq;
                uint32_t bh[2] = { Bhi[n*18 + kb], Bhi[n*18 + kb + 4] };
                uint32_t bl[2] = { Blo[n*18 + kb], Blo[n*18 + kb + 4] };
                #pragma unroll
                for (int mi = 0; mi < 2; mi++) {
                    mma16816(acc[mi][ni], ah[mi], bh);
                    mma16816(acc[mi][ni], ah[mi], bl);
                    mma16816(acc[mi][ni], al[mi], bh);
                }
            }
        }
        __syncthreads();
    }
    // epilogue: D frag (r,c0..1) + (r+8,c0..1)
    #pragma unroll
    for (int mi = 0; mi < 2; mi++) {
        size_t r0 = (size_t)blockIdx.y*128 + wm + mi*16 + gq;
        #pragma unroll
        for (int ni = 0; ni < 8; ni++) {
            int col = blockIdx.x*128 + wn + ni*8 + tq*2;
            float2 b2 = *(const float2*)(bias + col);
            float2 o0, o1;
            o0.x = acc[mi][ni][0] + b2.x; o0.y = acc[mi][ni][1] + b2.y;
            o1.x = acc[mi][ni][2] + b2.x; o1.y = acc[mi][ni][3] + b2.y;
            *(float2*)(C + r0*N + col) = o0;
            *(float2*)(C + (r0+8)*N + col) = o1;
        }
    }
}

// ---------------------------------------------------------------------------
// P1: build gate weights split Wx (K=256) / Whh (K=512); rp = 4*j + g.
// ---------------------------------------------------------------------------
__global__ __launch_bounds__(256) void k_wcat(
    const float* __restrict__ W_ih, const float* __restrict__ in2x_w,
    const float* __restrict__ in2x_b, const float* __restrict__ b_ih,
    const float* __restrict__ b_hh, const float* __restrict__ W_hh,
    float* __restrict__ Wx, float* __restrict__ Whh, float* __restrict__ bcomb)
{
    int rp = blockIdx.x;
    int g = rp & 3, j = rp >> 2;
    int orow = g*HH + j;
    int tid = threadIdx.x;
    __shared__ float wrow[EE];
    __shared__ float red[256];
    wrow[tid] = W_ih[orow*EE + tid];
    __syncthreads();
    float s = 0.f;
    #pragma unroll 8
    for (int i = 0; i < EE; i++) s += wrow[i] * in2x_w[i*1280 + tid];
    Wx[rp*EE + tid] = s;
    Whh[rp*HH + tid]       = W_hh[orow*HH + tid];
    Whh[rp*HH + 256 + tid] = W_hh[orow*HH + 256 + tid];
    red[tid] = wrow[tid] * in2x_b[tid];
    __syncthreads();
    for (int st = 128; st > 0; st >>= 1) {
        if (tid < st) red[tid] += red[tid+st];
        __syncthreads();
    }
    if (tid == 0) bcomb[rp] = red[0] + b_ih[orow] + b_hh[orow];
}

__global__ __launch_bounds__(256) void k_u(
    const float* __restrict__ Wpg, const float* __restrict__ in2x_w,
    float* __restrict__ u)
{
    int j = threadIdx.x;
    float s = 0.f;
    #pragma unroll 8
    for (int i = 0; i < EE; i++) s += Wpg[2048 + i] * in2x_w[i*1280 + j];
    u[j] = s;
}

__global__ __launch_bounds__(256) void k_sx(
    const float* __restrict__ inp, const float* __restrict__ u,
    const float* __restrict__ Wpg_b, float* __restrict__ sx)
{
    int w = blockIdx.x*8 + (threadIdx.x >> 5);
    int lane = threadIdx.x & 31;
    const float* row = inp + (size_t)w*EE;
    float s = 0.f;
    #pragma unroll
    for (int q = 0; q < 8; q++) s += row[lane + 32*q] * u[lane + 32*q];
    #pragma unroll
    for (int o = 16; o > 0; o >>= 1) s += __shfl_xor_sync(0xffffffffu, s, o);
    if (lane == 0) sx[w] = s + Wpg_b[0];
}

// ---------------------------------------------------------------------------
// Fused recurrence step: gates[b, nbase..+64] = h@Whh^T (+gx incl bias) -> LSTM.
// grid 32 (64 gate-cols each = 16 units), 1024 threads = 4 K-quadrants of 256.
// ---------------------------------------------------------------------------
#define STEP_SMEM 69632
__global__ __launch_bounds__(1024) void k_step(
    const float* __restrict__ hsrc, const float* __restrict__ csrc,
    const float* __restrict__ gx, const float* __restrict__ Whh,
    float* __restrict__ hdst, float* __restrict__ cdst)
{
    extern __shared__ float sm[];
    int tid = threadIdx.x;
    int q = tid >> 8, qt = tid & 255;
    float* Asq = sm + q*4352;
    float* Wsq = Asq + 2176;
    int nbase = blockIdx.x * 64;
    int m = qt >> 2, kq = qt & 3;
    int tr = qt >> 4, tc = qt & 15;
    int koff = q * 128;
    float acc[4][4];
    #pragma unroll
    for (int i = 0; i < 4; i++)
        #pragma unroll
        for (int jj = 0; jj < 4; jj++) acc[i][jj] = 0.f;

    const float* Wp = Whh + (size_t)(nbase + m)*HH;

    #pragma unroll
    for (int k0 = 0; k0 < 128; k0 += 32) {
        #pragma unroll
        for (int qq = 0; qq < 2; qq++) {
            int kk0 = qq*16 + kq*4;
            int kg = koff + k0 + kk0;
            float4 a4 = *(const float4*)(hsrc + m*HH + kg);
            float4 w4 = *(const float4*)(Wp + kg);
            Asq[(kk0+0)*68+m] = a4.x; Asq[(kk0+1)*68+m] = a4.y;
            Asq[(kk0+2)*68+m] = a4.z; Asq[(kk0+3)*68+m] = a4.w;
            Wsq[(kk0+0)*68+m] = w4.x; Wsq[(kk0+1)*68+m] = w4.y;
            Wsq[(kk0+2)*68+m] = w4.z; Wsq[(kk0+3)*68+m] = w4.w;
        }
        __syncthreads();
        #pragma unroll
        for (int k = 0; k < 32; k++) {
            float4 av = *(const float4*)&Asq[k*68 + tr*4];
            float4 wv = *(const float4*)&Wsq[k*68 + tc*4];
            float a_[4] = {av.x, av.y, av.z, av.w};
            float w_[4] = {wv.x, wv.y, wv.z, wv.w};
            #pragma unroll
            for (int i = 0; i < 4; i++)
                #pragma unroll
                for (int jj = 0; jj < 4; jj++)
                    acc[i][jj] += a_[i]*w_[jj];
        }
        __syncthreads();
    }
    float* part = sm;
    #pragma unroll
    for (int i = 0; i < 4; i++)
        #pragma unroll
        for (int jj = 0; jj < 4; jj++)
            part[q*4096 + (tr*4+i)*64 + tc*4 + jj] = acc[i][jj];
    __syncthreads();
    {
        int b = tid >> 4, u = tid & 15;
        float gi = 0.f, gf = 0.f, gg = 0.f, go = 0.f;
        #pragma unroll
        for (int s = 0; s < 4; s++) {
            const float* pp = part + s*4096 + b*64 + u*4;
            gi += pp[0]; gf += pp[1]; gg += pp[2]; go += pp[3];
        }
        const float* gxp = gx + (size_t)b*H4 + nbase + u*4;
        gi += gxp[0]; gf += gxp[1]; gg += gxp[2]; go += gxp[3];
        float iv = sigmoidf_(gi);
        float fv = sigmoidf_(gf);
        float gv = tanhf(gg);
        float ov = sigmoidf_(go);
        int j = blockIdx.x*16 + u;
        float cn = fv * csrc[b*HH + j] + iv * gv;
        float hn = ov * tanhf(cn);
        cdst[b*HH + j] = cn;
        hdst[b*HH + j] = hn;
    }
}

// ---------------------------------------------------------------------------
// Batched scores: grid (25, 64). Warp owns 2 l-rows in registers, loops 64 t.
// ---------------------------------------------------------------------------
__global__ __launch_bounds__(256) void k_scores_all(
    const float* __restrict__ ef, const float* __restrict__ dec_all,
    const float* __restrict__ v, float* __restrict__ e_all)
{
    int chunk = blockIdx.x, b = blockIdx.y;
    int warp = threadIdx.x >> 5, lane = threadIdx.x & 31;
    int l0 = chunk*16 + warp*2;

    const float4* efr0 = (const float4*)(ef + ((size_t)b*LL + l0)*HH);
    const float4* efr1 = (const float4*)(ef + ((size_t)b*LL + l0 + 1)*HH);
    const float4* vp   = (const float4*)v;
    float4 f0[4], f1[4], vv[4];
    #pragma unroll
    for (int q = 0; q < 4; q++) {
        f0[q] = efr0[lane + 32*q];
        f1[q] = efr1[lane + 32*q];
        vv[q] = vp  [lane + 32*q];
    }
    for (int t = 0; t < TT; t++) {
        const float4* dp = (const float4*)(dec_all + ((size_t)(t*BB + b))*HH);
        float s0 = 0.f, s1 = 0.f;
        #pragma unroll
        for (int q = 0; q < 4; q++) {
            float4 d = dp[lane + 32*q];
            s0 += vv[q].x*ftanh(f0[q].x + d.x) + vv[q].y*ftanh(f0[q].y + d.y)
                + vv[q].z*ftanh(f0[q].z + d.z) + vv[q].w*ftanh(f0[q].w + d.w);
            s1 += vv[q].x*ftanh(f1[q].x + d.x) + vv[q].y*ftanh(f1[q].y + d.y)
                + vv[q].z*ftanh(f1[q].z + d.z) + vv[q].w*ftanh(f1[q].w + d.w);
        }
        #pragma unroll
        for (int o = 16; o > 0; o >>= 1) {
            s0 += __shfl_xor_sync(0xffffffffu, s0, o);
            s1 += __shfl_xor_sync(0xffffffffu, s1, o);
        }
        if (lane == 0) {
            float* er = e_all + ((size_t)(t*BB + b))*LL + l0;
            er[0] = s0; er[1] = s1;
        }
    }
}

__global__ __launch_bounds__(256) void k_softmax(
    const float* __restrict__ e_all, const float* __restrict__ mask,
    float* __restrict__ attn)
{
    int r = blockIdx.x*8 + (threadIdx.x >> 5);
    int lane = threadIdx.x & 31;
    int b = r & 63;
    const float* er = e_all + (size_t)r*LL;
    const float* mr = mask + b*LL;
    float ev[13];
    float mx = -1e30f;
    #pragma unroll
    for (int i = 0; i < 13; i++) {
        int l = lane + 32*i;
        ev[i] = (l < LL) ? er[l] : -1e30f;
        mx = fmaxf(mx, ev[i]);
    }
    #pragma unroll
    for (int o = 16; o > 0; o >>= 1) mx = fmaxf(mx, __shfl_xor_sync(0xffffffffu, mx, o));
    float sum = 0.f;
    #pragma unroll
    for (int i = 0; i < 13; i++) {
        int l = lane + 32*i;
        float val = (l < LL) ? __expf(ev[i] - mx) * mr[l] : 0.f;
        ev[i] = val;
        sum += val;
    }
    #pragma unroll
    for (int o = 16; o > 0; o >>= 1) sum += __shfl_xor_sync(0xffffffffu, sum, o);
    float inv = 1.f / sum;
    #pragma unroll
    for (int i = 0; i < 13; i++) {
        int l = lane + 32*i;
        if (l < LL) attn[(size_t)r*LL + l] = ev[i] * inv;
    }
}

// ---------------------------------------------------------------------------
// Batched ctx per-b GEMM: C[t,e] = sum_l a[t,b,l]*es[b,l,e]; grid (16,64).
// ---------------------------------------------------------------------------
__global__ __launch_bounds__(256) void k_ctx(
    const float* __restrict__ attn, const float* __restrict__ es,
    float* __restrict__ ctx_all)
{
    __shared__ float As[16][68];
    __shared__ float Bs[16][68];
    int tid = threadIdx.x;
    int b = blockIdx.y, e0 = blockIdx.x*64;
    int tr = tid >> 4, tc = tid & 15;
    float acc[4][4];
    #pragma unroll
    for (int i = 0; i < 4; i++)
        #pragma unroll
        for (int jj = 0; jj < 4; jj++) acc[i][jj] = 0.f;

    int at = tid >> 2, ak4 = (tid & 3)*4;
    int bk = tid >> 4, be4 = (tid & 15)*4;

    for (int it = 0; it < 25; it++) {
        int l0 = it*16;
        float4 a4 = *(const float4*)(attn + ((size_t)at*BB + b)*LL + l0 + ak4);
        As[ak4+0][at] = a4.x; As[ak4+1][at] = a4.y;
        As[ak4+2][at] = a4.z; As[ak4+3][at] = a4.w;
        float4 b4 = *(const float4*)(es + ((size_t)(b*LL + l0 + bk))*H2 + e0 + be4);
        *(float4*)&Bs[bk][be4] = b4;
        __syncthreads();
        #pragma unroll
        for (int k = 0; k < 16; k++) {
            float4 av = *(const float4*)&As[k][tr*4];
            float4 bv = *(const float4*)&Bs[k][tc*4];
            float a_[4] = {av.x, av.y, av.z, av.w};
            float b_[4] = {bv.x, bv.y, bv.z, bv.w};
            #pragma unroll
            for (int i = 0; i < 4; i++)
                #pragma unroll
                for (int jj = 0; jj < 4; jj++)
                    acc[i][jj] += a_[i]*b_[jj];
        }
        __syncthreads();
    }
    #pragma unroll
    for (int i = 0; i < 4; i++) {
        int t = tr*4 + i;
        float4 o = make_float4(acc[i][0], acc[i][1], acc[i][2], acc[i][3]);
        *(float4*)(ctx_all + ((size_t)t*BB + b)*H2 + e0 + tc*4) = o;
    }
}

__global__ __launch_bounds__(256) void k_pgen(
    const float* __restrict__ ctx_all, const float* __restrict__ h_all,
    const float* __restrict__ c_all, const float* __restrict__ Wpg,
    const float* __restrict__ sx, float* __restrict__ pg)
{
    int r = blockIdx.x*8 + (threadIdx.x >> 5);
    int lane = threadIdx.x & 31;
    const float4* cx = (const float4*)(ctx_all + (size_t)r*H2);
    const float4* hp = (const float4*)(h_all + (size_t)r*HH);
    const float4* cp = (const float4*)(c_all + (size_t)r*HH);
    const float4* w  = (const float4*)Wpg;
    float s = 0.f;
    #pragma unroll
    for (int q = 0; q < 8; q++) {
        float4 f = cx[lane + 32*q], ww = w[lane + 32*q];
        s += f.x*ww.x + f.y*ww.y + f.z*ww.z + f.w*ww.w;
    }
    #pragma unroll
    for (int q = 0; q < 4; q++) {
        float4 f = hp[lane + 32*q], ww = w[256 + lane + 32*q];
        s += f.x*ww.x + f.y*ww.y + f.z*ww.z + f.w*ww.w;
    }
    #pragma unroll
    for (int q = 0; q < 4; q++) {
        float4 f = cp[lane + 32*q], ww = w[384 + lane + 32*q];
        s += f.x*ww.x + f.y*ww.y + f.z*ww.z + f.w*ww.w;
    }
    #pragma unroll
    for (int o = 16; o > 0; o >>= 1) s += __shfl_xor_sync(0xffffffffu, s, o);
    if (lane == 0) pg[r] = 1.f/(1.f + __expf(-(s + sx[r])));
}

__global__ __launch_bounds__(256) void k_copy_hc(
    const float* __restrict__ h, const float* __restrict__ c, float* __restrict__ out)
{
    int i = blockIdx.x*256 + threadIdx.x;
    out[OUT_H + i] = h[i];
    out[OUT_C + i] = c[i];
}

// ---------------------------------------------------------------------------
extern "C" void kernel_launch(void* const* d_in, const int* in_sizes, int n_in,
                              void* d_out, int out_size)
{
    const float* dec_in     = (const float*)d_in[0];
    const float* init_h     = (const float*)d_in[1];
    const float* init_c     = (const float*)d_in[2];
    const float* enc_states = (const float*)d_in[3];
    const float* maskp      = (const float*)d_in[4];
    const float* Ws_w       = (const float*)d_in[5];
    const float* Ws_b       = (const float*)d_in[6];
    const float* in2x_w     = (const float*)d_in[7];
    const float* in2x_b     = (const float*)d_in[8];
    const float* Wpg_w      = (const float*)d_in[9];
    const float* Wpg_b      = (const float*)d_in[10];
    const float* Wout_w     = (const float*)d_in[11];
    const float* Wout_b     = (const float*)d_in[12];
    const float* Wh_w       = (const float*)d_in[13];
    const float* Wh_b       = (const float*)d_in[14];
    const float* vptr       = (const float*)d_in[15];
    const float* W_ih       = (const float*)d_in[16];
    const float* W_hh       = (const float*)d_in[17];
    const float* b_ih       = (const float*)d_in[18];
    const float* b_hh       = (const float*)d_in[19];
    float* out = (float*)d_out;

    float *p_ef, *p_wx, *p_whh, *p_bc, *p_u, *p_sx, *p_gx;
    float *p_ha, *p_ca, *p_da, *p_ea, *p_xa;
    cudaGetSymbolAddress((void**)&p_ef,   g_enc_feat);
    cudaGetSymbolAddress((void**)&p_wx,   g_Wx);
    cudaGetSymbolAddress((void**)&p_whh,  g_Whh);
    cudaGetSymbolAddress((void**)&p_bc,   g_bcomb);
    cudaGetSymbolAddress((void**)&p_u,    g_u);
    cudaGetSymbolAddress((void**)&p_sx,   g_sx);
    cudaGetSymbolAddress((void**)&p_gx,   g_gx_all);
    cudaGetSymbolAddress((void**)&p_ha,   g_h_all);
    cudaGetSymbolAddress((void**)&p_ca,   g_c_all);
    cudaGetSymbolAddress((void**)&p_da,   g_dec_all);
    cudaGetSymbolAddress((void**)&p_ea,   g_e_all);
    cudaGetSymbolAddress((void**)&p_xa,   g_ctx_all);

    cudaFuncSetAttribute(k_step, cudaFuncAttributeMaxDynamicSharedMemorySize, STEP_SMEM);

    // Precompute (off recurrence path)
    k_wcat<<<H4, 256>>>(W_ih, in2x_w, in2x_b, b_ih, b_hh, W_hh, p_wx, p_whh, p_bc);
    k_u<<<1, 256>>>(Wpg_w, in2x_w, p_u);
    k_sx<<<512, 256>>>(dec_in, p_u, Wpg_b, p_sx);
    // gates_x[t,b] = inp @ Wx^T + bcomb  (M=4096, K=256, N=2048) — tensor cores
    k_bmma<<<dim3(H4/128, (TT*BB)/128), 256>>>(dec_in, EE, dec_in, 0,
                                               p_wx, p_bc, p_gx, H4);

    // Fused LSTM recurrence: one kernel per step
    for (int t = 0; t < TT; t++) {
        const float* hsrc = (t == 0) ? init_h : p_ha + (size_t)(t - 1)*BH;
        const float* csrc = (t == 0) ? init_c : p_ca + (size_t)(t - 1)*BH;
        k_step<<<32, 1024, STEP_SMEM>>>(hsrc, csrc, p_gx + (size_t)t*BB*H4,
                                        p_whh, p_ha + (size_t)t*BH,
                                        p_ca + (size_t)t*BH);
    }

    // enc_feat = enc_states @ Wh^T + Wh_b  (M=25600, K=1024, N=512) — tensor cores
    k_bmma<<<dim3(HH/128, (BB*LL)/128), 256>>>(enc_states, H2, enc_states, 0,
                                               Wh_w, Wh_b, p_ef, HH);
    // dec_all = [h_all|c_all] @ Ws^T + Ws_b  (M=4096, K=1024, N=512) — tensor cores
    k_bmma<<<dim3(HH/128, (TT*BB)/128), 256>>>(p_ha, HH, p_ca, HH,
                                               Ws_w, Ws_b, p_da, HH);
    // scores for all (t,b,l)
    k_scores_all<<<dim3(25, 64), 256>>>(p_ef, p_da, vptr, p_ea);
    // masked renormalized softmax -> attn
    k_softmax<<<512, 256>>>(p_ea, maskp, out + OUT_ATTN);
    // ctx for all t
    k_ctx<<<dim3(16, 64), 256>>>(out + OUT_ATTN, enc_states, p_xa);
    // p_gen
    k_pgen<<<512, 256>>>(p_xa, p_ha, p_ca, Wpg_w, p_sx, out + OUT_PG);
    // outputs = [h_all|ctx_all] @ Wout^T + Wout_b  (K=1536) — tensor cores
    k_bmma<<<dim3(HH/128, (TT*BB)/128), 256>>>(p_ha, HH, p_xa, H2,
                                               Wout_w, Wout_b, out + OUT_OUTPUTS, HH);
    k_copy_hc<<<128, 256>>>(p_ha + (size_t)(TT-1)*BH, p_ca + (size_t)(TT-1)*BH, out);
}

// round 10
// speedup vs baseline: 1.4264x; 1.4264x over previous
#include <cuda_runtime.h>
#include <cuda_bf16.h>
#include <math.h>
#include <stdint.h>

// Problem constants
#define BB 64
#define TT 64
#define LL 400
#define EE 256
#define HH 512
#define H2 1024      // 2H
#define H4 2048      // 4H
#define BH (BB*HH)   // 32768

// d_out layout: outputs[T,B,H] | h[B,H] | c[B,H] | attn[T,B,L] | p_gens[T,B,1]
#define OUT_OUTPUTS 0
#define OUT_H  2097152
#define OUT_C  2129920
#define OUT_ATTN 2162688
#define OUT_PG 3801088

// ---------------- scratch (static device arrays; no allocation) ----------------
__device__ float g_enc_feat[BB*LL*HH];       // 52.4 MB
__device__ float g_Wx[H4*EE];
__device__ float g_Whh[H4*HH];
__device__ float g_bcomb[H4];
__device__ float g_u[EE];
__device__ float g_sx[TT*BB];
__device__ float g_gx_all[TT*BB*H4];         // x-part of gates (incl bias), all t
__device__ float g_gpart[4*BB*H4];           // recurrence split-K partials
__device__ float g_h_all[TT*BB*HH];
__device__ float g_c_all[TT*BB*HH];
__device__ float g_dec_all[TT*BB*HH];
__device__ float g_e_all[TT*BB*LL];
__device__ float g_ctx_all[TT*BB*H2];

__device__ __forceinline__ float sigmoidf_(float x) { return 1.f/(1.f+__expf(-x)); }
// fast-but-accurate tanh: abs err ~1e-7 (NOT tanh.approx, which is ~6e-4)
__device__ __forceinline__ float ftanh(float x) {
    float e = __expf(2.f*x);
    return 1.f - __fdividef(2.f, e + 1.f);
}
__device__ __forceinline__ uint32_t packbf2(float a, float b) {
    __nv_bfloat162 t = __floats2bfloat162_rn(a, b);
    return *reinterpret_cast<uint32_t*>(&t);
}
__device__ __forceinline__ float residf(float a) {
    return a - __bfloat162float(__float2bfloat16(a));
}
// mma.sync m16n8k16 bf16 -> f32 accum (arch-agnostic tensor core path)
__device__ __forceinline__ void mma16816(float* d, const uint32_t* a, const uint32_t* b) {
    asm volatile(
        "mma.sync.aligned.m16n8k16.row.col.f32.bf16.bf16.f32 "
        "{%0,%1,%2,%3}, {%4,%5,%6,%7}, {%8,%9}, {%0,%1,%2,%3};\n"
        : "+f"(d[0]), "+f"(d[1]), "+f"(d[2]), "+f"(d[3])
        : "r"(a[0]), "r"(a[1]), "r"(a[2]), "r"(a[3]), "r"(b[0]), "r"(b[1]));
}

// ---------------------------------------------------------------------------
// bf16x3 tensor-core GEMM: C[m,n] = [A0|A1][m,:].W[n,:] + bias[n]
// fp32 in/out. A sources row-major (K-major), W [N,K] row-major.
// M,N multiples of 128; K multiple of 32; concat split w0 multiple of 16.
// Tile 128x128, BK=32, 256 threads = 8 warps (4M x 2N), each warp 32x64.
// ---------------------------------------------------------------------------
__global__ __launch_bounds__(256) void k_bmma(
    const float* __restrict__ A0, int w0,
    const float* __restrict__ A1, int w1,
    const float* __restrict__ W, const float* __restrict__ bias,
    float* __restrict__ C, int N)
{
    // padded stride 18 u32 (36 bf16) per row -> conflict-free quad access
    __shared__ uint32_t Ahi[128*18], Alo[128*18], Bhi[128*18], Blo[128*18];
    int tid = threadIdx.x;
    int lane = tid & 31, wid = tid >> 5;
    int wm = (wid & 3)*32, wn = (wid >> 2)*64;
    int K = w0 + w1;

    float acc[2][8][4];
    #pragma unroll
    for (int mi = 0; mi < 2; mi++)
        #pragma unroll
        for (int ni = 0; ni < 8; ni++)
            #pragma unroll
            for (int q = 0; q < 4; q++) acc[mi][ni][q] = 0.f;

    int lrow = tid >> 1;             // conversion row 0..127
    int lcol = (tid & 1)*16;         // float col base within 32-chunk
    size_t aRow = (size_t)blockIdx.y*128 + lrow;
    size_t wRow = (size_t)blockIdx.x*128 + lrow;
    int sbase = lrow*18 + (lcol >> 1);
    int gq = lane >> 2, tq = lane & 3;

    for (int kc = 0; kc < K; kc += 32) {
        int kg = kc + lcol;
        const float* asrc = (kg < w0) ? A0 + aRow*w0 + kg
                                      : A1 + aRow*w1 + (kg - w0);
        const float* wsrc = W + wRow*K + kg;
        #pragma unroll
        for (int g = 0; g < 4; g++) {
            float4 f = *(const float4*)(asrc + g*4);
            Ahi[sbase + g*2]     = packbf2(f.x, f.y);
            Ahi[sbase + g*2 + 1] = packbf2(f.z, f.w);
            Alo[sbase + g*2]     = packbf2(residf(f.x), residf(f.y));
            Alo[sbase + g*2 + 1] = packbf2(residf(f.z), residf(f.w));
            float4 h = *(const float4*)(wsrc + g*4);
            Bhi[sbase + g*2]     = packbf2(h.x, h.y);
            Bhi[sbase + g*2 + 1] = packbf2(h.z, h.w);
            Blo[sbase + g*2]     = packbf2(residf(h.x), residf(h.y));
            Blo[sbase + g*2 + 1] = packbf2(residf(h.z), residf(h.w));
        }
        __syncthreads();
        #pragma unroll
        for (int ks = 0; ks < 2; ks++) {
            int kb = ks*8 + tq;
            uint32_t ah[2][4], al[2][4];
            #pragma unroll
            for (int mi = 0; mi < 2; mi++) {
                int r = wm + mi*16 + gq;
                ah[mi][0] = Ahi[r*18 + kb];
                ah[mi][1] = Ahi[(r+8)*18 + kb];
                ah[mi][2] = Ahi[r*18 + kb + 4];
                ah[mi][3] = Ahi[(r+8)*18 + kb + 4];
                al[mi][0] = Alo[r*18 + kb];
                al[mi][1] = Alo[(r+8)*18 + kb];
                al[mi][2] = Alo[r*18 + kb + 4];
                al[mi][3] = Alo[(r+8)*18 + kb + 4];
            }
            #pragma unroll
            for (int ni = 0; ni < 8; ni++) {
                int n = wn + ni*8 + gq;
                uint32_t bh[2] = { Bhi[n*18 + kb], Bhi[n*18 + kb + 4] };
                uint32_t bl[2] = { Blo[n*18 + kb], Blo[n*18 + kb + 4] };
                #pragma unroll
                for (int mi = 0; mi < 2; mi++) {
                    mma16816(acc[mi][ni], ah[mi], bh);
                    mma16816(acc[mi][ni], ah[mi], bl);
                    mma16816(acc[mi][ni], al[mi], bh);
                }
            }
        }
        __syncthreads();
    }
    // epilogue: D frag (r,c0..1) + (r+8,c0..1)
    #pragma unroll
    for (int mi = 0; mi < 2; mi++) {
        size_t r0 = (size_t)blockIdx.y*128 + wm + mi*16 + gq;
        #pragma unroll
        for (int ni = 0; ni < 8; ni++) {
            int col = blockIdx.x*128 + wn + ni*8 + tq*2;
            float2 b2 = *(const float2*)(bias + col);
            float2 o0, o1;
            o0.x = acc[mi][ni][0] + b2.x; o0.y = acc[mi][ni][1] + b2.y;
            o1.x = acc[mi][ni][2] + b2.x; o1.y = acc[mi][ni][3] + b2.y;
            *(float2*)(C + r0*N + col) = o0;
            *(float2*)(C + (r0+8)*N + col) = o1;
        }
    }
}

// ---------------------------------------------------------------------------
// P1: build gate weights split Wx (K=256) / Whh (K=512); rp = 4*j + g.
// ---------------------------------------------------------------------------
__global__ __launch_bounds__(256) void k_wcat(
    const float* __restrict__ W_ih, const float* __restrict__ in2x_w,
    const float* __restrict__ in2x_b, const float* __restrict__ b_ih,
    const float* __restrict__ b_hh, const float* __restrict__ W_hh,
    float* __restrict__ Wx, float* __restrict__ Whh, float* __restrict__ bcomb)
{
    int rp = blockIdx.x;
    int g = rp & 3, j = rp >> 2;
    int orow = g*HH + j;
    int tid = threadIdx.x;
    __shared__ float wrow[EE];
    __shared__ float red[256];
    wrow[tid] = W_ih[orow*EE + tid];
    __syncthreads();
    float s = 0.f;
    #pragma unroll 8
    for (int i = 0; i < EE; i++) s += wrow[i] * in2x_w[i*1280 + tid];
    Wx[rp*EE + tid] = s;
    Whh[rp*HH + tid]       = W_hh[orow*HH + tid];
    Whh[rp*HH + 256 + tid] = W_hh[orow*HH + 256 + tid];
    red[tid] = wrow[tid] * in2x_b[tid];
    __syncthreads();
    for (int st = 128; st > 0; st >>= 1) {
        if (tid < st) red[tid] += red[tid+st];
        __syncthreads();
    }
    if (tid == 0) bcomb[rp] = red[0] + b_ih[orow] + b_hh[orow];
}

__global__ __launch_bounds__(256) void k_u(
    const float* __restrict__ Wpg, const float* __restrict__ in2x_w,
    float* __restrict__ u)
{
    int j = threadIdx.x;
    float s = 0.f;
    #pragma unroll 8
    for (int i = 0; i < EE; i++) s += Wpg[2048 + i] * in2x_w[i*1280 + j];
    u[j] = s;
}

__global__ __launch_bounds__(256) void k_sx(
    const float* __restrict__ inp, const float* __restrict__ u,
    const float* __restrict__ Wpg_b, float* __restrict__ sx)
{
    int w = blockIdx.x*8 + (threadIdx.x >> 5);
    int lane = threadIdx.x & 31;
    const float* row = inp + (size_t)w*EE;
    float s = 0.f;
    #pragma unroll
    for (int q = 0; q < 8; q++) s += row[lane + 32*q] * u[lane + 32*q];
    #pragma unroll
    for (int o = 16; o > 0; o >>= 1) s += __shfl_xor_sync(0xffffffffu, s, o);
    if (lane == 0) sx[w] = s + Wpg_b[0];
}

// ---------------------------------------------------------------------------
// Split-K GEMM for per-step h @ Whh^T: Cpart[ks][m][n], Kchunk=128.
// grid (N/64, K/128) = (32, 4) = 128 blocks, 256 threads, 4x4/thread.
// ---------------------------------------------------------------------------
__global__ __launch_bounds__(256) void k_gemm_sk(
    const float* __restrict__ src, int K,
    const float* __restrict__ W,
    float* __restrict__ Cpart, int N)
{
    __shared__ float As[32][68];
    __shared__ float Ws[32][68];
    int tid = threadIdx.x;
    int m = tid >> 2, kq = tid & 3;
    int tr = tid >> 4, tc = tid & 15;
    int koff = blockIdx.y * 128;
    int nbase = blockIdx.x * 64;
    float acc[4][4];
    #pragma unroll
    for (int i = 0; i < 4; i++)
        #pragma unroll
        for (int jj = 0; jj < 4; jj++) acc[i][jj] = 0.f;

    const float* Wp = W + (size_t)(nbase + m)*K;

    #pragma unroll
    for (int k0 = 0; k0 < 128; k0 += 32) {
        #pragma unroll
        for (int q = 0; q < 2; q++) {
            int kk0 = q*16 + kq*4;
            int kg = koff + k0 + kk0;
            float4 a4 = *(const float4*)(src + m*K + kg);
            float4 w4 = *(const float4*)(Wp + kg);
            As[kk0+0][m] = a4.x; As[kk0+1][m] = a4.y; As[kk0+2][m] = a4.z; As[kk0+3][m] = a4.w;
            Ws[kk0+0][m] = w4.x; Ws[kk0+1][m] = w4.y; Ws[kk0+2][m] = w4.z; Ws[kk0+3][m] = w4.w;
        }
        __syncthreads();
        #pragma unroll
        for (int k = 0; k < 32; k++) {
            float4 av = *(const float4*)&As[k][tr*4];
            float4 wv = *(const float4*)&Ws[k][tc*4];
            float a_[4] = {av.x, av.y, av.z, av.w};
            float w_[4] = {wv.x, wv.y, wv.z, wv.w};
            #pragma unroll
            for (int i = 0; i < 4; i++)
                #pragma unroll
                for (int jj = 0; jj < 4; jj++)
                    acc[i][jj] += a_[i]*w_[jj];
        }
        __syncthreads();
    }
    #pragma unroll
    for (int i = 0; i < 4; i++) {
        int row = tr*4 + i;
        float4 o = make_float4(acc[i][0], acc[i][1], acc[i][2], acc[i][3]);
        *(float4*)(Cpart + ((size_t)blockIdx.y*64 + row)*N + nbase + tc*4) = o;
    }
}

// ---------------------------------------------------------------------------
// S2: gates = gates_x[t] + sum of 4 h-partials -> LSTM elementwise -> h,c
// ---------------------------------------------------------------------------
__global__ __launch_bounds__(256) void k_lstm_ew(
    const float* __restrict__ gpart, const float* __restrict__ gx,
    const float* __restrict__ csrc, float* __restrict__ hdst,
    float* __restrict__ cdst)
{
    int idx = blockIdx.x*256 + threadIdx.x;   // 0..32767
    int b = idx >> 9, j = idx & 511;
    float4 g = ((const float4*)(gx + (size_t)b*H4))[j];
    #pragma unroll
    for (int ks = 0; ks < 4; ks++) {
        float4 p = ((const float4*)(gpart + (size_t)ks*BB*H4 + b*H4))[j];
        g.x += p.x; g.y += p.y; g.z += p.z; g.w += p.w;
    }
    float iv = sigmoidf_(g.x);
    float fv = sigmoidf_(g.y);
    float gv = tanhf(g.z);
    float ov = sigmoidf_(g.w);
    float cn = fv * csrc[b*HH + j] + iv * gv;
    float hn = ov * tanhf(cn);
    cdst[b*HH + j] = cn;
    hdst[b*HH + j] = hn;
}

// ---------------------------------------------------------------------------
// Batched scores: grid (25, 64). Warp owns 2 l-rows in registers, loops 64 t.
// ---------------------------------------------------------------------------
__global__ __launch_bounds__(256) void k_scores_all(
    const float* __restrict__ ef, const float* __restrict__ dec_all,
    const float* __restrict__ v, float* __restrict__ e_all)
{
    int chunk = blockIdx.x, b = blockIdx.y;
    int warp = threadIdx.x >> 5, lane = threadIdx.x & 31;
    int l0 = chunk*16 + warp*2;

    const float4* efr0 = (const float4*)(ef + ((size_t)b*LL + l0)*HH);
    const float4* efr1 = (const float4*)(ef + ((size_t)b*LL + l0 + 1)*HH);
    const float4* vp   = (const float4*)v;
    float4 f0[4], f1[4], vv[4];
    #pragma unroll
    for (int q = 0; q < 4; q++) {
        f0[q] = efr0[lane + 32*q];
        f1[q] = efr1[lane + 32*q];
        vv[q] = vp  [lane + 32*q];
    }
    for (int t = 0; t < TT; t++) {
        const float4* dp = (const float4*)(dec_all + ((size_t)(t*BB + b))*HH);
        float s0 = 0.f, s1 = 0.f;
        #pragma unroll
        for (int q = 0; q < 4; q++) {
            float4 d = dp[lane + 32*q];
            s0 += vv[q].x*ftanh(f0[q].x + d.x) + vv[q].y*ftanh(f0[q].y + d.y)
                + vv[q].z*ftanh(f0[q].z + d.z) + vv[q].w*ftanh(f0[q].w + d.w);
            s1 += vv[q].x*ftanh(f1[q].x + d.x) + vv[q].y*ftanh(f1[q].y + d.y)
                + vv[q].z*ftanh(f1[q].z + d.z) + vv[q].w*ftanh(f1[q].w + d.w);
        }
        #pragma unroll
        for (int o = 16; o > 0; o >>= 1) {
            s0 += __shfl_xor_sync(0xffffffffu, s0, o);
            s1 += __shfl_xor_sync(0xffffffffu, s1, o);
        }
        if (lane == 0) {
            float* er = e_all + ((size_t)(t*BB + b))*LL + l0;
            er[0] = s0; er[1] = s1;
        }
    }
}

__global__ __launch_bounds__(256) void k_softmax(
    const float* __restrict__ e_all, const float* __restrict__ mask,
    float* __restrict__ attn)
{
    int r = blockIdx.x*8 + (threadIdx.x >> 5);
    int lane = threadIdx.x & 31;
    int b = r & 63;
    const float* er = e_all + (size_t)r*LL;
    const float* mr = mask + b*LL;
    float ev[13];
    float mx = -1e30f;
    #pragma unroll
    for (int i = 0; i < 13; i++) {
        int l = lane + 32*i;
        ev[i] = (l < LL) ? er[l] : -1e30f;
        mx = fmaxf(mx, ev[i]);
    }
    #pragma unroll
    for (int o = 16; o > 0; o >>= 1) mx = fmaxf(mx, __shfl_xor_sync(0xffffffffu, mx, o));
    float sum = 0.f;
    #pragma unroll
    for (int i = 0; i < 13; i++) {
        int l = lane + 32*i;
        float val = (l < LL) ? __expf(ev[i] - mx) * mr[l] : 0.f;
        ev[i] = val;
        sum += val;
    }
    #pragma unroll
    for (int o = 16; o > 0; o >>= 1) sum += __shfl_xor_sync(0xffffffffu, sum, o);
    float inv = 1.f / sum;
    #pragma unroll
    for (int i = 0; i < 13; i++) {
        int l = lane + 32*i;
        if (l < LL) attn[(size_t)r*LL + l] = ev[i] * inv;
    }
}

// ---------------------------------------------------------------------------
// Batched ctx per-b GEMM: C[t,e] = sum_l a[t,b,l]*es[b,l,e]; grid (16,64).
// ---------------------------------------------------------------------------
__global__ __launch_bounds__(256) void k_ctx(
    const float* __restrict__ attn, const float* __restrict__ es,
    float* __restrict__ ctx_all)
{
    __shared__ float As[16][68];
    __shared__ float Bs[16][68];
    int tid = threadIdx.x;
    int b = blockIdx.y, e0 = blockIdx.x*64;
    int tr = tid >> 4, tc = tid & 15;
    float acc[4][4];
    #pragma unroll
    for (int i = 0; i < 4; i++)
        #pragma unroll
        for (int jj = 0; jj < 4; jj++) acc[i][jj] = 0.f;

    int at = tid >> 2, ak4 = (tid & 3)*4;
    int bk = tid >> 4, be4 = (tid & 15)*4;

    for (int it = 0; it < 25; it++) {
        int l0 = it*16;
        float4 a4 = *(const float4*)(attn + ((size_t)at*BB + b)*LL + l0 + ak4);
        As[ak4+0][at] = a4.x; As[ak4+1][at] = a4.y;
        As[ak4+2][at] = a4.z; As[ak4+3][at] = a4.w;
        float4 b4 = *(const float4*)(es + ((size_t)(b*LL + l0 + bk))*H2 + e0 + be4);
        *(float4*)&Bs[bk][be4] = b4;
        __syncthreads();
        #pragma unroll
        for (int k = 0; k < 16; k++) {
            float4 av = *(const float4*)&As[k][tr*4];
            float4 bv = *(const float4*)&Bs[k][tc*4];
            float a_[4] = {av.x, av.y, av.z, av.w};
            float b_[4] = {bv.x, bv.y, bv.z, bv.w};
            #pragma unroll
            for (int i = 0; i < 4; i++)
                #pragma unroll
                for (int jj = 0; jj < 4; jj++)
                    acc[i][jj] += a_[i]*b_[jj];
        }
        __syncthreads();
    }
    #pragma unroll
    for (int i = 0; i < 4; i++) {
        int t = tr*4 + i;
        float4 o = make_float4(acc[i][0], acc[i][1], acc[i][2], acc[i][3]);
        *(float4*)(ctx_all + ((size_t)t*BB + b)*H2 + e0 + tc*4) = o;
    }
}

__global__ __launch_bounds__(256) void k_pgen(
    const float* __restrict__ ctx_all, const float* __restrict__ h_all,
    const float* __restrict__ c_all, const float* __restrict__ Wpg,
    const float* __restrict__ sx, float* __restrict__ pg)
{
    int r = blockIdx.x*8 + (threadIdx.x >> 5);
    int lane = threadIdx.x & 31;
    const float4* cx = (const float4*)(ctx_all + (size_t)r*H2);
    const float4* hp = (const float4*)(h_all + (size_t)r*HH);
    const float4* cp = (const float4*)(c_all + (size_t)r*HH);
    const float4* w  = (const float4*)Wpg;
    float s = 0.f;
    #pragma unroll
    for (int q = 0; q < 8; q++) {
        float4 f = cx[lane + 32*q], ww = w[lane + 32*q];
        s += f.x*ww.x + f.y*ww.y + f.z*ww.z + f.w*ww.w;
    }
    #pragma unroll
    for (int q = 0; q < 4; q++) {
        float4 f = hp[lane + 32*q], ww = w[256 + lane + 32*q];
        s += f.x*ww.x + f.y*ww.y + f.z*ww.z + f.w*ww.w;
    }
    #pragma unroll
    for (int q = 0; q < 4; q++) {
        float4 f = cp[lane + 32*q], ww = w[384 + lane + 32*q];
        s += f.x*ww.x + f.y*ww.y + f.z*ww.z + f.w*ww.w;
    }
    #pragma unroll
    for (int o = 16; o > 0; o >>= 1) s += __shfl_xor_sync(0xffffffffu, s, o);
    if (lane == 0) pg[r] = 1.f/(1.f + __expf(-(s + sx[r])));
}

__global__ __launch_bounds__(256) void k_copy_hc(
    const float* __restrict__ h, const float* __restrict__ c, float* __restrict__ out)
{
    int i = blockIdx.x*256 + threadIdx.x;
    out[OUT_H + i] = h[i];
    out[OUT_C + i] = c[i];
}

// ---------------------------------------------------------------------------
extern "C" void kernel_launch(void* const* d_in, const int* in_sizes, int n_in,
                              void* d_out, int out_size)
{
    const float* dec_in     = (const float*)d_in[0];
    const float* init_h     = (const float*)d_in[1];
    const float* init_c     = (const float*)d_in[2];
    const float* enc_states = (const float*)d_in[3];
    const float* maskp      = (const float*)d_in[4];
    const float* Ws_w       = (const float*)d_in[5];
    const float* Ws_b       = (const float*)d_in[6];
    const float* in2x_w     = (const float*)d_in[7];
    const float* in2x_b     = (const float*)d_in[8];
    const float* Wpg_w      = (const float*)d_in[9];
    const float* Wpg_b      = (const float*)d_in[10];
    const float* Wout_w     = (const float*)d_in[11];
    const float* Wout_b     = (const float*)d_in[12];
    const float* Wh_w       = (const float*)d_in[13];
    const float* Wh_b       = (const float*)d_in[14];
    const float* vptr       = (const float*)d_in[15];
    const float* W_ih       = (const float*)d_in[16];
    const float* W_hh       = (const float*)d_in[17];
    const float* b_ih       = (const float*)d_in[18];
    const float* b_hh       = (const float*)d_in[19];
    float* out = (float*)d_out;

    float *p_ef, *p_wx, *p_whh, *p_bc, *p_u, *p_sx, *p_gx, *p_gp;
    float *p_ha, *p_ca, *p_da, *p_ea, *p_xa;
    cudaGetSymbolAddress((void**)&p_ef,   g_enc_feat);
    cudaGetSymbolAddress((void**)&p_wx,   g_Wx);
    cudaGetSymbolAddress((void**)&p_whh,  g_Whh);
    cudaGetSymbolAddress((void**)&p_bc,   g_bcomb);
    cudaGetSymbolAddress((void**)&p_u,    g_u);
    cudaGetSymbolAddress((void**)&p_sx,   g_sx);
    cudaGetSymbolAddress((void**)&p_gx,   g_gx_all);
    cudaGetSymbolAddress((void**)&p_gp,   g_gpart);
    cudaGetSymbolAddress((void**)&p_ha,   g_h_all);
    cudaGetSymbolAddress((void**)&p_ca,   g_c_all);
    cudaGetSymbolAddress((void**)&p_da,   g_dec_all);
    cudaGetSymbolAddress((void**)&p_ea,   g_e_all);
    cudaGetSymbolAddress((void**)&p_xa,   g_ctx_all);

    // Precompute (off recurrence path)
    k_wcat<<<H4, 256>>>(W_ih, in2x_w, in2x_b, b_ih, b_hh, W_hh, p_wx, p_whh, p_bc);
    k_u<<<1, 256>>>(Wpg_w, in2x_w, p_u);
    k_sx<<<512, 256>>>(dec_in, p_u, Wpg_b, p_sx);
    // gates_x[t,b] = inp @ Wx^T + bcomb  (M=4096, K=256, N=2048) — tensor cores
    k_bmma<<<dim3(H4/128, (TT*BB)/128), 256>>>(dec_in, EE, dec_in, 0,
                                               p_wx, p_bc, p_gx, H4);

    // LSTM recurrence: split-K h-GEMM (128 blocks) + reduce/elementwise (128 blocks)
    for (int t = 0; t < TT; t++) {
        const float* hsrc = (t == 0) ? init_h : p_ha + (size_t)(t - 1)*BH;
        const float* csrc = (t == 0) ? init_c : p_ca + (size_t)(t - 1)*BH;
        k_gemm_sk<<<dim3(32, 4), 256>>>(hsrc, HH, p_whh, p_gp, H4);
        k_lstm_ew<<<128, 256>>>(p_gp, p_gx + (size_t)t*BB*H4, csrc,
                                p_ha + (size_t)t*BH, p_ca + (size_t)t*BH);
    }

    // enc_feat = enc_states @ Wh^T + Wh_b  (M=25600, K=1024, N=512) — tensor cores
    k_bmma<<<dim3(HH/128, (BB*LL)/128), 256>>>(enc_states, H2, enc_states, 0,
                                               Wh_w, Wh_b, p_ef, HH);
    // dec_all = [h_all|c_all] @ Ws^T + Ws_b  (M=4096, K=1024, N=512) — tensor cores
    k_bmma<<<dim3(HH/128, (TT*BB)/128), 256>>>(p_ha, HH, p_ca, HH,
                                               Ws_w, Ws_b, p_da, HH);
    // scores for all (t,b,l)
    k_scores_all<<<dim3(25, 64), 256>>>(p_ef, p_da, vptr, p_ea);
    // masked renormalized softmax -> attn
    k_softmax<<<512, 256>>>(p_ea, maskp, out + OUT_ATTN);
    // ctx for all t
    k_ctx<<<dim3(16, 64), 256>>>(out + OUT_ATTN, enc_states, p_xa);
    // p_gen
    k_pgen<<<512, 256>>>(p_xa, p_ha, p_ca, Wpg_w, p_sx, out + OUT_PG);
    // outputs = [h_all|ctx_all] @ Wout^T + Wout_b  (K=1536) — tensor cores
    k_bmma<<<dim3(HH/128, (TT*BB)/128), 256>>>(p_ha, HH, p_xa, H2,
                                               Wout_w, Wout_b, out + OUT_OUTPUTS, HH);
    k_copy_hc<<<128, 256>>>(p_ha + (size_t)(TT-1)*BH, p_ca + (size_t)(TT-1)*BH, out);
}